// round 7
// baseline (speedup 1.0000x reference)
#include <cuda_runtime.h>
#include <cuda_bf16.h>
#include <math.h>
#include <stdint.h>

// Problem dims
#define BB  32      // batch
#define SS  100     // src len
#define TT  64      // trg len
#define HH  512     // hidden
#define EE  512     // embed
#define VV  32000   // vocab
#define G4H 2048    // 4*H
#define KZ  1536    // 2E + H (fused gate input)
#define NBLK 128    // persistent-kernel grid (co-resident on 148 SMs)

// ---------------- device scratch (static globals; no runtime alloc) ----------------
__device__ float g_W4[G4H * KZ];     // fused [W_ih | W_hh], rows reordered to 4*h+gate
__device__ float g_b4[G4H];          // fused bias, same reorder
__device__ float g_Wqb[HH * HH];     // Wb @ Wq
__device__ float g_bqb[HH];          // Wb @ bq + bb
__device__ float g_P[BB * SS * HH];  // Wqb^T-projected memory (step-invariant)
__device__ float g_q0[BB * SS];      // bqb . mem (+ mask folded as -1e9)
__device__ float g_h[2][BB * HH];    // hidden ping-pong
__device__ float g_c[BB * HH];       // cell
__device__ float g_ctx[BB * HH];     // attention context
__device__ float g_u[BB * HH];       // tanh(MLP) intermediate
__device__ float g_out[TT * BB * EE];// all decoder outputs (T,B,E)
__device__ int   g_trg64;            // 1 if trg buffer is int64
__device__ int   g_maskty;           // 0=uint8, 1=int32, 2=float32

// grid barrier state (monotonic generation across graph replays; wrap-safe)
__device__ volatile unsigned g_cnt;
__device__ volatile unsigned g_gen;

// bf16 hi/lo splits for tensor-core logits GEMM
__device__ unsigned short g_Bh[(size_t)VV * EE];  // emb hi
__device__ unsigned short g_Bl[(size_t)VV * EE];  // emb lo
__device__ unsigned short g_Ah[(size_t)TT * BB * EE]; // out hi
__device__ unsigned short g_Al[(size_t)TT * BB * EE]; // out lo

// ---------------- helpers ----------------
__device__ __forceinline__ uint32_t smem_u32(const void* p) {
    uint32_t a;
    asm("{ .reg .u64 t; cvta.to.shared.u64 t, %1; cvt.u32.u64 %0, t; }" : "=r"(a) : "l"(p));
    return a;
}

__device__ __forceinline__ void ldm_x4(uint32_t* r, uint32_t addr) {
    asm volatile("ldmatrix.sync.aligned.m8n8.x4.shared.b16 {%0,%1,%2,%3}, [%4];"
                 : "=r"(r[0]), "=r"(r[1]), "=r"(r[2]), "=r"(r[3]) : "r"(addr));
}

__device__ __forceinline__ void mma_bf16(float* d, const uint32_t* a, uint32_t b0, uint32_t b1) {
    asm volatile(
        "mma.sync.aligned.m16n8k16.row.col.f32.bf16.bf16.f32 "
        "{%0,%1,%2,%3}, {%4,%5,%6,%7}, {%8,%9}, {%0,%1,%2,%3};"
        : "+f"(d[0]), "+f"(d[1]), "+f"(d[2]), "+f"(d[3])
        : "r"(a[0]), "r"(a[1]), "r"(a[2]), "r"(a[3]), "r"(b0), "r"(b1));
}

// sense-reversing grid barrier: tight spin, no nanosleep
__device__ __forceinline__ void gsync() {
    __syncthreads();
    if (threadIdx.x == 0) {
        __threadfence();                       // publish this block's writes
        unsigned gen = g_gen;
        if (atomicAdd((unsigned*)&g_cnt, 1u) == NBLK - 1) {
            g_cnt = 0;
            __threadfence();                   // cnt reset visible before release
            g_gen = gen + 1;
        } else {
            while (g_gen == gen) { }           // volatile spin, ~L2 latency per poll
        }
        __threadfence();                       // acquire: see released writes
    }
    __syncthreads();
}

// ---------------- dtype detection + state init (fused; launch #1) ----------------
__global__ void detect_init(const int* __restrict__ trg_w, const int* __restrict__ mask_w,
                            const float* __restrict__ ih, const float* __restrict__ ic) {
    __shared__ int s_odd_nz, s_bin, s_f32;
    if (threadIdx.x == 0) { s_odd_nz = 0; s_bin = 1; s_f32 = 1; }
    __syncthreads();
    for (int i = threadIdx.x; i < (BB * TT) / 2; i += blockDim.x)
        if (trg_w[2 * i + 1] != 0) atomicOr(&s_odd_nz, 1);
    for (int i = threadIdx.x; i < (BB * SS) / 4; i += blockDim.x) {
        int v = mask_w[i];
        if (v != 0 && v != 1)           atomicAnd(&s_bin, 0);
        if (v != 0 && v != 0x3f800000)  atomicAnd(&s_f32, 0);
    }
    for (int i = threadIdx.x; i < BB * HH; i += blockDim.x) {
        g_h[0][i] = ih[i]; g_c[i] = ic[i];
    }
    __syncthreads();
    if (threadIdx.x == 0) {
        g_trg64 = s_odd_nz ? 0 : 1;
        g_maskty = s_bin ? 1 : (s_f32 ? 2 : 0);
    }
}

// ---------------- prep kernels ----------------
__global__ void prep_w4(const float* __restrict__ Wih, const float* __restrict__ Whh,
                        const float* __restrict__ bih, const float* __restrict__ bhh) {
    int rr = blockIdx.x;
    int h = rr >> 2, g = rr & 3;
    int j = g * HH + h;
    for (int k = threadIdx.x; k < KZ; k += blockDim.x) {
        float v = (k < 2 * EE) ? Wih[j * (2 * EE) + k] : Whh[j * HH + (k - 2 * EE)];
        g_W4[rr * KZ + k] = v;
    }
    if (threadIdx.x == 0) g_b4[rr] = bih[j] + bhh[j];
}

__global__ void prep_wqb(const float* __restrict__ Wq, const float* __restrict__ Wb,
                         const float* __restrict__ bq, const float* __restrict__ bbias) {
    int r = blockIdx.y * 16 + threadIdx.y;
    int c = blockIdx.x * 16 + threadIdx.x;
    float acc = 0.f;
    for (int k = 0; k < HH; k++) acc += Wb[r * HH + k] * Wq[k * HH + c];
    g_Wqb[r * HH + c] = acc;
    if (blockIdx.x == 0 && threadIdx.x == 0) {
        float a = bbias[r];
        for (int k = 0; k < HH; k++) a += Wb[r * HH + k] * bq[k];
        g_bqb[r] = a;
    }
}

// split fp32 -> bf16 hi + bf16 lo (float4 granularity)
__global__ void conv_split(const float* __restrict__ src,
                           unsigned short* __restrict__ hi,
                           unsigned short* __restrict__ lo, int n4) {
    int i = blockIdx.x * 256 + threadIdx.x;
    if (i >= n4) return;
    float4 v = ((const float4*)src)[i];
    __nv_bfloat16 h0 = __float2bfloat16(v.x);
    __nv_bfloat16 h1 = __float2bfloat16(v.y);
    __nv_bfloat16 h2 = __float2bfloat16(v.z);
    __nv_bfloat16 h3 = __float2bfloat16(v.w);
    __nv_bfloat16 l0 = __float2bfloat16(v.x - __bfloat162float(h0));
    __nv_bfloat16 l1 = __float2bfloat16(v.y - __bfloat162float(h1));
    __nv_bfloat16 l2 = __float2bfloat16(v.z - __bfloat162float(h2));
    __nv_bfloat16 l3 = __float2bfloat16(v.w - __bfloat162float(h3));
    __nv_bfloat162* H = (__nv_bfloat162*)hi;
    __nv_bfloat162* L = (__nv_bfloat162*)lo;
    H[2 * i]     = __halves2bfloat162(h0, h1);
    H[2 * i + 1] = __halves2bfloat162(h2, h3);
    L[2 * i]     = __halves2bfloat162(l0, l1);
    L[2 * i + 1] = __halves2bfloat162(l2, l3);
}

// ---------------- P = mem_flat(3200,512) @ Wqb(512,512)  (fp32 tiled GEMM) ----------------
__global__ void __launch_bounds__(256) pgemm(const float* __restrict__ mem) {
    __shared__ float As[16][68];
    __shared__ float Bs[16][68];
    int tid = threadIdx.x;
    int m0 = blockIdx.y * 64, j0 = blockIdx.x * 64;
    int tx = tid & 15, ty = tid >> 4;

    float acc[4][4];
    #pragma unroll
    for (int i = 0; i < 4; i++)
        #pragma unroll
        for (int j = 0; j < 4; j++) acc[i][j] = 0.f;

    for (int k0 = 0; k0 < HH; k0 += 16) {
        int row = tid >> 2, kq = (tid & 3) * 4;
        float4 va = *(const float4*)(mem + (size_t)(m0 + row) * HH + k0 + kq);
        As[kq][row] = va.x; As[kq + 1][row] = va.y;
        As[kq + 2][row] = va.z; As[kq + 3][row] = va.w;
        int kr = tid >> 4, jq = (tid & 15) * 4;
        float4 vb = *(const float4*)(g_Wqb + (size_t)(k0 + kr) * HH + j0 + jq);
        *(float4*)&Bs[kr][jq] = vb;
        __syncthreads();
        #pragma unroll
        for (int k = 0; k < 16; k++) {
            float a[4], b[4];
            #pragma unroll
            for (int i = 0; i < 4; i++) a[i] = As[k][ty * 4 + i];
            #pragma unroll
            for (int i = 0; i < 4; i++) b[i] = Bs[k][tx * 4 + i];
            #pragma unroll
            for (int i = 0; i < 4; i++)
                #pragma unroll
                for (int j = 0; j < 4; j++) acc[i][j] += a[i] * b[j];
        }
        __syncthreads();
    }
    #pragma unroll
    for (int i = 0; i < 4; i++)
        #pragma unroll
        for (int j = 0; j < 4; j++)
            g_P[(size_t)(m0 + ty * 4 + i) * HH + j0 + tx * 4 + j] = acc[i][j];
}

// q0[m] = bqb . mem[m]  (mask folded: masked -> -1e9)
__global__ void q0_kernel(const float* __restrict__ mem, const void* __restrict__ mask_raw) {
    int m = blockIdx.x * 8 + (threadIdx.x >> 5);
    int l = threadIdx.x & 31;
    if (m >= BB * SS) return;
    float a = 0.f;
    for (int k = l; k < HH; k += 32) a += g_bqb[k] * mem[(size_t)m * HH + k];
    #pragma unroll
    for (int off = 16; off; off >>= 1) a += __shfl_down_sync(0xffffffffu, a, off);
    if (l == 0) {
        int mty = g_maskty;
        bool mv;
        if      (mty == 0) mv = ((const unsigned char*)mask_raw)[m] != 0;
        else if (mty == 1) mv = ((const int*)mask_raw)[m] != 0;
        else               mv = ((const float*)mask_raw)[m] != 0.0f;
        g_q0[m] = mv ? a : -1e9f;
    }
}

// ---------------- persistent decoder loop: all 64 steps in ONE kernel ----------------
__global__ void __launch_bounds__(256) decoder_loop(
    const float* __restrict__ emb, const void* __restrict__ trg_raw,
    const float* __restrict__ mem, const float* __restrict__ init_output,
    const float* __restrict__ Wo1, const float* __restrict__ bo1,
    const float* __restrict__ Wo2, const float* __restrict__ bo2)
{
    __shared__ union {
        struct { float Zs[64][33]; float2 Wp[64][9]; float Gs[16][33]; int tok[BB]; } a;
        struct { float q[HH]; float sc[128]; } c;
        struct { float Zs[128][33]; float Ws[4][130]; float red[4][32]; } d;
    } sm;

    int tid = threadIdx.x, wid = tid >> 5, lane = tid & 31;
    int bid = blockIdx.x;
    int w3 = wid & 3, kh = wid >> 2;

    for (int t = 0; t < TT; t++) {
        const float* out_prev = (t == 0) ? init_output : (g_out + (size_t)(t - 1) * BB * EE);
        const float* h_prev = g_h[t & 1];
        float*       h_cur  = g_h[(t + 1) & 1];

        // ---- Phase A: gates GEMM + LSTM elementwise (block bid -> 16 gate rows) ----
        {
            int rbase = bid * 16;
            if (tid < BB) {
                long long v;
                if (g_trg64) v = ((const long long*)trg_raw)[tid * TT + t];
                else         v = ((const int*)trg_raw)[tid * TT + t];
                int tk = (int)v;
                if (tk < 0) tk = 0;
                if (tk >= VV) tk = VV - 1;
                sm.a.tok[tid] = tk;
            }
            __syncthreads();

            float acc0 = 0.f, acc1 = 0.f;
            for (int kt = 0; kt < KZ / 64; kt++) {
                int kg0 = kt * 64;
                for (int i = tid; i < 2048; i += 256) {
                    int b = i >> 6, k = i & 63, kg = kg0 + k;
                    float v;
                    if      (kg < EE)      v = emb[(size_t)sm.a.tok[b] * EE + kg];
                    else if (kg < 2 * EE)  v = out_prev[b * EE + (kg - EE)];
                    else                   v = h_prev[b * HH + (kg - 2 * EE)];
                    sm.a.Zs[k][b] = v;
                }
                // weight row pairs packed: Wp[k][w] = {row w, row w+8}
                for (int i = tid; i < 1024; i += 256) {
                    int r = i >> 6, k = i & 63;
                    float v = g_W4[(rbase + r) * KZ + kg0 + k];
                    ((float*)sm.a.Wp)[k * 18 + (r & 7) * 2 + (r >> 3)] = v;
                }
                __syncthreads();
                #pragma unroll
                for (int kk = 0; kk < 64; kk++) {
                    float z = sm.a.Zs[kk][lane];
                    float2 wv = sm.a.Wp[kk][wid];
                    acc0 += wv.x * z;
                    acc1 += wv.y * z;
                }
                __syncthreads();
            }
            sm.a.Gs[wid][lane]     = acc0 + g_b4[rbase + wid];
            sm.a.Gs[wid + 8][lane] = acc1 + g_b4[rbase + wid + 8];
            __syncthreads();

            if (tid < 128) {
                int hl = tid >> 5, b = tid & 31;
                float gi = sm.a.Gs[4 * hl + 0][b];
                float gf = sm.a.Gs[4 * hl + 1][b];
                float gg = sm.a.Gs[4 * hl + 2][b];
                float go = sm.a.Gs[4 * hl + 3][b];
                gi = 1.f / (1.f + expf(-gi));
                gf = 1.f / (1.f + expf(-gf));
                go = 1.f / (1.f + expf(-go));
                gg = tanhf(gg);
                int h = bid * 4 + hl;
                int idx = b * HH + h;
                float c = gf * g_c[idx] + gi * gg;
                g_c[idx] = c;
                h_cur[idx] = go * tanhf(c);
            }
        }
        gsync();

        // ---- Phase C: attention (blocks 0..31, one per batch) ----
        if (bid < BB) {
            int b = bid;
            for (int i = tid; i < HH; i += 256) sm.c.q[i] = h_cur[b * HH + i];
            __syncthreads();

            for (int s = wid; s < SS; s += 8) {
                const float* prow = g_P + (size_t)(b * SS + s) * HH;
                float a = 0.f;
                for (int k = lane; k < HH; k += 32) a += sm.c.q[k] * prow[k];
                #pragma unroll
                for (int off = 16; off; off >>= 1) a += __shfl_down_sync(0xffffffffu, a, off);
                if (lane == 0) sm.c.sc[s] = a + g_q0[b * SS + s];
            }
            __syncthreads();

            if (wid == 0) {
                float m = -1e30f;
                for (int s = lane; s < SS; s += 32) m = fmaxf(m, sm.c.sc[s]);
                #pragma unroll
                for (int off = 16; off; off >>= 1) m = fmaxf(m, __shfl_xor_sync(0xffffffffu, m, off));
                float sum = 0.f;
                for (int s = lane; s < SS; s += 32) {
                    float e = expf(sm.c.sc[s] - m); sm.c.sc[s] = e; sum += e;
                }
                #pragma unroll
                for (int off = 16; off; off >>= 1) sum += __shfl_xor_sync(0xffffffffu, sum, off);
                float inv = 1.f / sum;
                for (int s = lane; s < SS; s += 32) sm.c.sc[s] *= inv;
            }
            __syncthreads();

            for (int h = tid; h < HH; h += 256) {
                float a = 0.f;
                #pragma unroll 4
                for (int s = 0; s < SS; s++) a += sm.c.sc[s] * mem[(size_t)(b * SS + s) * HH + h];
                g_ctx[b * HH + h] = a;
            }
        }
        gsync();

        // ---- Phase D1: u = tanh(Wo1 [h|ctx] + bo1). 8 warps: 4 rows x 2 K-halves ----
        {
            int r0 = bid * 4;
            float acc = 0.f;
            for (int kt = 0; kt < 8; kt++) {
                int kgA = kt * 64;          // K half 0: [0,512)   -> h_cur
                int kgB = 512 + kt * 64;    // K half 1: [512,1024)-> ctx
                for (int i = tid; i < 4096; i += 256) {
                    int b = i >> 7, kk = i & 127;
                    int kg = (kk < 64) ? (kgA + kk) : (kgB + kk - 64);
                    float v = (kg < HH) ? h_cur[b * HH + kg] : g_ctx[b * HH + (kg - HH)];
                    sm.d.Zs[kk][b] = v;
                }
                for (int i = tid; i < 512; i += 256) {
                    int r = i >> 7, kk = i & 127;
                    int kg = (kk < 64) ? (kgA + kk) : (kgB + kk - 64);
                    sm.d.Ws[r][kk] = Wo1[(size_t)(r0 + r) * (2 * HH) + kg];
                }
                __syncthreads();
                #pragma unroll
                for (int kk = 0; kk < 64; kk++)
                    acc += sm.d.Ws[w3][kh * 64 + kk] * sm.d.Zs[kh * 64 + kk][lane];
                __syncthreads();
            }
            if (kh == 1) sm.d.red[w3][lane] = acc;
            __syncthreads();
            if (kh == 0) {
                acc += sm.d.red[w3][lane];
                g_u[lane * HH + r0 + w3] = tanhf(acc + bo1[r0 + w3]);
            }
        }
        gsync();

        // ---- Phase D2: out = Wo2 u + bo2. 8 warps: 4 rows x 2 K-halves (K=512) ----
        {
            int r0 = bid * 4;
            float acc = 0.f;
            for (int kt = 0; kt < 4; kt++) {
                int kgA = kt * 64;          // K half 0: [0,256)
                int kgB = 256 + kt * 64;    // K half 1: [256,512)
                for (int i = tid; i < 4096; i += 256) {
                    int b = i >> 7, kk = i & 127;
                    int kg = (kk < 64) ? (kgA + kk) : (kgB + kk - 64);
                    sm.d.Zs[kk][b] = g_u[b * HH + kg];
                }
                for (int i = tid; i < 512; i += 256) {
                    int r = i >> 7, kk = i & 127;
                    int kg = (kk < 64) ? (kgA + kk) : (kgB + kk - 64);
                    sm.d.Ws[r][kk] = Wo2[(size_t)(r0 + r) * HH + kg];
                }
                __syncthreads();
                #pragma unroll
                for (int kk = 0; kk < 64; kk++)
                    acc += sm.d.Ws[w3][kh * 64 + kk] * sm.d.Zs[kh * 64 + kk][lane];
                __syncthreads();
            }
            if (kh == 1) sm.d.red[w3][lane] = acc;
            __syncthreads();
            if (kh == 0)
                g_out[((size_t)t * BB + lane) * EE + r0 + w3] =
                    acc + sm.d.red[w3][lane] + bo2[r0 + w3];
        }
        gsync();
    }
}

// ---------------- HMMA logits GEMM ----------------
#define SPAD 72
__global__ void __launch_bounds__(256, 2) logits_mma(float* __restrict__ outp)
{
    __shared__ __align__(16) unsigned short sA[128 * SPAD];
    __shared__ __align__(16) unsigned short sB[128 * SPAD];

    int tid = threadIdx.x, lane = tid & 31, wid = tid >> 5;
    int wm = wid >> 2;
    int wn = wid & 3;
    int mblk = blockIdx.x * 128;
    int nblk = blockIdx.y * 128;

    uint32_t aA = smem_u32(sA);
    uint32_t aB = smem_u32(sB);
    uint32_t abase = aA + (uint32_t)((wm * 64 + (lane & 15)) * SPAD * 2 + (lane >> 4) * 16);
    uint32_t bbase = aB + (uint32_t)((wn * 32 + (lane & 15)) * SPAD * 2 + (lane >> 4) * 16);

    float acc[4][4][4];
    #pragma unroll
    for (int i = 0; i < 4; i++)
        #pragma unroll
        for (int j = 0; j < 4; j++)
            #pragma unroll
            for (int k = 0; k < 4; k++) acc[i][j][k] = 0.f;

    for (int c = 0; c < 24; c++) {
        int pass = c >> 3;
        int kb = (c & 7) * 64;
        const unsigned short* Ap = (pass == 2) ? g_Al : g_Ah;
        const unsigned short* Bp = (pass == 1) ? g_Bl : g_Bh;

        __syncthreads();
        #pragma unroll
        for (int u = 0; u < 4; u++) {
            int unit = u * 256 + tid;
            int row = unit >> 3, seg = unit & 7;
            uint4 va = *(const uint4*)(Ap + (size_t)(mblk + row) * 512 + kb + seg * 8);
            *(uint4*)(sA + row * SPAD + seg * 8) = va;
            uint4 vb = *(const uint4*)(Bp + (size_t)(nblk + row) * 512 + kb + seg * 8);
            *(uint4*)(sB + row * SPAD + seg * 8) = vb;
        }
        __syncthreads();

        #pragma unroll
        for (int ks = 0; ks < 4; ks++) {
            uint32_t afr[4][4];
            #pragma unroll
            for (int mf = 0; mf < 4; mf++)
                ldm_x4(afr[mf], abase + (uint32_t)(mf * 16 * SPAD * 2 + ks * 32));
            uint32_t bfr[2][4];
            #pragma unroll
            for (int g = 0; g < 2; g++)
                ldm_x4(bfr[g], bbase + (uint32_t)(g * 16 * SPAD * 2 + ks * 32));
            #pragma unroll
            for (int mf = 0; mf < 4; mf++)
                #pragma unroll
                for (int nf = 0; nf < 4; nf++)
                    mma_bf16(acc[mf][nf], afr[mf],
                             bfr[nf >> 1][nf & 1], bfr[nf >> 1][(nf & 1) + 2]);
        }
    }

    #pragma unroll
    for (int mf = 0; mf < 4; mf++) {
        int r0 = mblk + wm * 64 + mf * 16 + (lane >> 2);
        #pragma unroll
        for (int half = 0; half < 2; half++) {
            int r = r0 + half * 8;
            int tt = r >> 5, b2 = r & 31;
            float* orow = outp + (size_t)(b2 * TT + tt) * VV + nblk + wn * 32 + (lane & 3) * 2;
            #pragma unroll
            for (int nf = 0; nf < 4; nf++) {
                float2 v = make_float2(acc[mf][nf][2 * half], acc[mf][nf][2 * half + 1]);
                *(float2*)(orow + nf * 8) = v;
            }
        }
    }
}

// ---------------- host launch ----------------
extern "C" void kernel_launch(void* const* d_in, const int* in_sizes, int n_in,
                              void* d_out, int out_size)
{
    const float* src_memory  = (const float*)d_in[0];
    const void*  src_mask    = d_in[1];
    const float* init_hidden = (const float*)d_in[2];
    const float* init_cell   = (const float*)d_in[3];
    const float* init_output = (const float*)d_in[4];
    const void*  trg         = d_in[5];
    const float* emb         = (const float*)d_in[6];
    const float* W_ih        = (const float*)d_in[7];
    const float* W_hh        = (const float*)d_in[8];
    const float* b_ih        = (const float*)d_in[9];
    const float* b_hh        = (const float*)d_in[10];
    const float* Wq          = (const float*)d_in[11];
    const float* bq          = (const float*)d_in[12];
    const float* Wb          = (const float*)d_in[13];
    const float* bbias       = (const float*)d_in[14];
    const float* Wo1         = (const float*)d_in[15];
    const float* bo1         = (const float*)d_in[16];
    const float* Wo2         = (const float*)d_in[17];
    const float* bo2         = (const float*)d_in[18];

    float *p_out;
    unsigned short *p_Bh, *p_Bl, *p_Ah, *p_Al;
    cudaGetSymbolAddress((void**)&p_out, g_out);
    cudaGetSymbolAddress((void**)&p_Bh,  g_Bh);
    cudaGetSymbolAddress((void**)&p_Bl,  g_Bl);
    cudaGetSymbolAddress((void**)&p_Ah,  g_Ah);
    cudaGetSymbolAddress((void**)&p_Al,  g_Al);

    // Order chosen so decoder_loop is launch #6 (ncu -s 5 -c 1 profiles it).
    detect_init<<<1, 256>>>((const int*)trg, (const int*)src_mask, init_hidden, init_cell);
    prep_wqb<<<dim3(32, 32), dim3(16, 16)>>>(Wq, Wb, bq, bbias);
    q0_kernel<<<(BB * SS) / 8, 256>>>(src_memory, src_mask);
    pgemm<<<dim3(HH / 64, (BB * SS) / 64), 256>>>(src_memory);
    prep_w4<<<G4H, 256>>>(W_ih, W_hh, b_ih, b_hh);

    decoder_loop<<<NBLK, 256>>>(emb, trg, src_memory, init_output, Wo1, bo1, Wo2, bo2);

    // bf16 splits + HMMA logits GEMM
    {
        int n4 = (VV * EE) / 4;
        conv_split<<<(n4 + 255) / 256, 256>>>(emb, p_Bh, p_Bl, n4);
    }
    {
        int n4 = (TT * BB * EE) / 4;
        conv_split<<<(n4 + 255) / 256, 256>>>(p_out, p_Ah, p_Al, n4);
    }
    logits_mma<<<dim3(16, 250), 256>>>((float*)d_out);
}

// round 8
// speedup vs baseline: 1.2689x; 1.2689x over previous
#include <cuda_runtime.h>
#include <cuda_bf16.h>
#include <math.h>
#include <stdint.h>

// Problem dims
#define BB  32
#define SS  100
#define TT  64
#define HH  512
#define EE  512
#define VV  32000
#define G4H 2048
#define KZ  1536     // E (emb) + H (u) + H (h)
#define NBLK 128

// ---------------- device scratch ----------------
__device__ float g_W4[G4H * KZ];     // [W_E | W_U | W_hh], rows reordered rr=4h+g
__device__ float g_b4[G4H];
__device__ float g_c0[G4H * BB];     // W_O @ init_output (t=0 bias), [rr][b]
__device__ float g_wob2[G4H];        // W_O @ bo2 (t>0 bias)
__device__ float g_Wqb[HH * HH];     // Wb @ Wq
__device__ float g_bqb[HH];          // Wb @ bq + bb
__device__ float g_P[BB * SS * HH];  // mem @ Wqb
__device__ float g_q0[BB * SS];      // bqb.mem with mask folded
__device__ float g_h[2][BB * HH];
__device__ float g_c[BB * HH];
__device__ float g_ctx[BB * HH];
__device__ float g_uall[TT * BB * HH]; // all u_t  (m = t*B+b)
__device__ float g_out[TT * BB * EE];  // out = uall @ Wo2^T + bo2
__device__ int   g_trg64;
__device__ int   g_maskty;

__device__ volatile unsigned g_cnt;
__device__ volatile unsigned g_gen;

__device__ unsigned short g_Bh[(size_t)VV * EE];
__device__ unsigned short g_Bl[(size_t)VV * EE];
__device__ unsigned short g_Ah[(size_t)TT * BB * EE];
__device__ unsigned short g_Al[(size_t)TT * BB * EE];

// ---------------- helpers ----------------
__device__ __forceinline__ uint32_t smem_u32(const void* p) {
    uint32_t a;
    asm("{ .reg .u64 t; cvta.to.shared.u64 t, %1; cvt.u32.u64 %0, t; }" : "=r"(a) : "l"(p));
    return a;
}
__device__ __forceinline__ void ldm_x4(uint32_t* r, uint32_t addr) {
    asm volatile("ldmatrix.sync.aligned.m8n8.x4.shared.b16 {%0,%1,%2,%3}, [%4];"
                 : "=r"(r[0]), "=r"(r[1]), "=r"(r[2]), "=r"(r[3]) : "r"(addr));
}
__device__ __forceinline__ void mma_bf16(float* d, const uint32_t* a, uint32_t b0, uint32_t b1) {
    asm volatile(
        "mma.sync.aligned.m16n8k16.row.col.f32.bf16.bf16.f32 "
        "{%0,%1,%2,%3}, {%4,%5,%6,%7}, {%8,%9}, {%0,%1,%2,%3};"
        : "+f"(d[0]), "+f"(d[1]), "+f"(d[2]), "+f"(d[3])
        : "r"(a[0]), "r"(a[1]), "r"(a[2]), "r"(a[3]), "r"(b0), "r"(b1));
}

// R6-proven barrier: nanosleep backoff spin
__device__ __forceinline__ void gsync() {
    __syncthreads();
    if (threadIdx.x == 0) {
        unsigned gen = g_gen;
        __threadfence();
        if (atomicAdd((unsigned*)&g_cnt, 1u) == NBLK - 1) {
            g_cnt = 0;
            __threadfence();
            g_gen = gen + 1;
        } else {
            while (g_gen == gen) __nanosleep(20);
        }
        __threadfence();
    }
    __syncthreads();
}

__device__ __forceinline__ int jmap(int rr) { return (rr & 3) * HH + (rr >> 2); }

// ---------------- prep1: detect/init + wqb + c0 + wob2 + w4(outer) ----------------
// blocks: [0] detect+init | [1,1025) wqb | [1025,1281) c0 | [1281,1345) wob2 | [1345,3393) w4
__global__ void __launch_bounds__(256) prep1(
    const int* __restrict__ trg_w, const int* __restrict__ mask_w,
    const float* __restrict__ ih, const float* __restrict__ ic,
    const float* __restrict__ Wq, const float* __restrict__ Wb,
    const float* __restrict__ bq, const float* __restrict__ bbias,
    const float* __restrict__ Wih, const float* __restrict__ Whh,
    const float* __restrict__ bih, const float* __restrict__ bhh,
    const float* __restrict__ init_output, const float* __restrict__ bo2)
{
    int bid = blockIdx.x, tid = threadIdx.x;
    int wid = tid >> 5, lane = tid & 31;

    if (bid == 0) {
        __shared__ int s_odd_nz, s_bin, s_f32;
        if (tid == 0) { s_odd_nz = 0; s_bin = 1; s_f32 = 1; }
        __syncthreads();
        for (int i = tid; i < (BB * TT) / 2; i += 256)
            if (trg_w[2 * i + 1] != 0) atomicOr(&s_odd_nz, 1);
        for (int i = tid; i < (BB * SS) / 4; i += 256) {
            int v = mask_w[i];
            if (v != 0 && v != 1)           atomicAnd(&s_bin, 0);
            if (v != 0 && v != 0x3f800000)  atomicAnd(&s_f32, 0);
        }
        for (int i = tid; i < BB * HH; i += 256) { g_h[0][i] = ih[i]; g_c[i] = ic[i]; }
        __syncthreads();
        if (tid == 0) {
            g_trg64 = s_odd_nz ? 0 : 1;
            g_maskty = s_bin ? 1 : (s_f32 ? 2 : 0);
        }
    } else if (bid < 1025) {
        // Wqb = Wb @ Wq ; bqb = Wb @ bq + bb
        int idx = bid - 1;
        int by = idx >> 5, bx = idx & 31;
        int ty = tid >> 4, tx = tid & 15;
        int r = by * 16 + ty, c = bx * 16 + tx;
        float acc = 0.f;
        for (int k = 0; k < HH; k++) acc += Wb[r * HH + k] * Wq[k * HH + c];
        g_Wqb[r * HH + c] = acc;
        if (bx == 0 && tx == 0) {
            float a = bbias[r];
            for (int k = 0; k < HH; k++) a += Wb[r * HH + k] * bq[k];
            g_bqb[r] = a;
        }
    } else if (bid < 1281) {
        // c0[rr][b] = sum_e W_O[rr,e] * init_output[b,e]
        int idx = bid - 1025;               // 0..255
        int rr = idx * 8 + wid;             // each warp one rr
        int j = jmap(rr);
        const float* wrow = Wih + (size_t)j * (2 * EE) + EE;
        for (int b = 0; b < BB; b++) {
            const float* io = init_output + (size_t)b * EE;
            float a = 0.f;
            for (int e = lane; e < EE; e += 32) a += wrow[e] * io[e];
            #pragma unroll
            for (int off = 16; off; off >>= 1) a += __shfl_down_sync(0xffffffffu, a, off);
            if (lane == 0) g_c0[rr * BB + b] = a;
        }
    } else if (bid < 1345) {
        // wob2[rr] = sum_e W_O[rr,e] * bo2[e]
        int idx = bid - 1281;               // 0..63
        for (int q = 0; q < 4; q++) {
            int rr = idx * 32 + wid * 4 + q;
            int j = jmap(rr);
            const float* wrow = Wih + (size_t)j * (2 * EE) + EE;
            float a = 0.f;
            for (int e = lane; e < EE; e += 32) a += wrow[e] * bo2[e];
            #pragma unroll
            for (int off = 16; off; off >>= 1) a += __shfl_down_sync(0xffffffffu, a, off);
            if (lane == 0) g_wob2[rr] = a;
        }
    } else {
        // g_W4 outer columns + b4
        int rr = bid - 1345;
        int j = jmap(rr);
        for (int k = tid; k < KZ; k += 256) {
            if (k < EE)            g_W4[(size_t)rr * KZ + k] = Wih[(size_t)j * (2 * EE) + k];
            else if (k >= 2 * EE)  g_W4[(size_t)rr * KZ + k] = Whh[(size_t)j * HH + (k - 2 * EE)];
            // middle filled by prep2 (W_U)
        }
        if (tid == 0) g_b4[rr] = bih[j] + bhh[j];
    }
}

// ---------------- prep2: pgemm + q0 + wu ----------------
// blocks: [0,400) pgemm | [400,800) q0 | [800,1056) wu
__global__ void __launch_bounds__(256) prep2(
    const float* __restrict__ mem, const void* __restrict__ mask_raw,
    const float* __restrict__ Wih, const float* __restrict__ Wo2)
{
    __shared__ float As[16][68];
    __shared__ float Bs[16][68];
    int bid = blockIdx.x, tid = threadIdx.x;

    if (bid < 400) {
        // P = mem_flat(3200,512) @ Wqb(512,512)
        int m0 = (bid >> 3) * 64, j0 = (bid & 7) * 64;
        int tx = tid & 15, ty = tid >> 4;
        float acc[4][4];
        #pragma unroll
        for (int i = 0; i < 4; i++)
            #pragma unroll
            for (int j = 0; j < 4; j++) acc[i][j] = 0.f;
        for (int k0 = 0; k0 < HH; k0 += 16) {
            int row = tid >> 2, kq = (tid & 3) * 4;
            float4 va = *(const float4*)(mem + (size_t)(m0 + row) * HH + k0 + kq);
            As[kq][row] = va.x; As[kq + 1][row] = va.y;
            As[kq + 2][row] = va.z; As[kq + 3][row] = va.w;
            int kr = tid >> 4, jq = (tid & 15) * 4;
            float4 vb = *(const float4*)(g_Wqb + (size_t)(k0 + kr) * HH + j0 + jq);
            *(float4*)&Bs[kr][jq] = vb;
            __syncthreads();
            #pragma unroll
            for (int k = 0; k < 16; k++) {
                float a[4], b[4];
                #pragma unroll
                for (int i = 0; i < 4; i++) a[i] = As[k][ty * 4 + i];
                #pragma unroll
                for (int i = 0; i < 4; i++) b[i] = Bs[k][tx * 4 + i];
                #pragma unroll
                for (int i = 0; i < 4; i++)
                    #pragma unroll
                    for (int j = 0; j < 4; j++) acc[i][j] += a[i] * b[j];
            }
            __syncthreads();
        }
        #pragma unroll
        for (int i = 0; i < 4; i++)
            #pragma unroll
            for (int j = 0; j < 4; j++)
                g_P[(size_t)(m0 + ty * 4 + i) * HH + j0 + tx * 4 + j] = acc[i][j];
    } else if (bid < 800) {
        // q0
        int m = (bid - 400) * 8 + (tid >> 5);
        int l = tid & 31;
        if (m < BB * SS) {
            float a = 0.f;
            for (int k = l; k < HH; k += 32) a += g_bqb[k] * mem[(size_t)m * HH + k];
            #pragma unroll
            for (int off = 16; off; off >>= 1) a += __shfl_down_sync(0xffffffffu, a, off);
            if (l == 0) {
                int mty = g_maskty;
                bool mv;
                if      (mty == 0) mv = ((const unsigned char*)mask_raw)[m] != 0;
                else if (mty == 1) mv = ((const int*)mask_raw)[m] != 0;
                else               mv = ((const float*)mask_raw)[m] != 0.0f;
                g_q0[m] = mv ? a : -1e9f;
            }
        }
    } else {
        // W_U = W_O(2048x512, reordered rows) @ Wo2(512x512) -> g_W4 middle cols
        int idx = bid - 800;
        int r0 = (idx >> 3) * 64, h0 = (idx & 7) * 64;
        int tx = tid & 15, ty = tid >> 4;
        float acc[4][4];
        #pragma unroll
        for (int i = 0; i < 4; i++)
            #pragma unroll
            for (int j = 0; j < 4; j++) acc[i][j] = 0.f;
        for (int k0 = 0; k0 < EE; k0 += 16) {
            int row = tid >> 2, kq = (tid & 3) * 4;
            int j = jmap(r0 + row);
            float4 va = *(const float4*)(Wih + (size_t)j * (2 * EE) + EE + k0 + kq);
            As[kq][row] = va.x; As[kq + 1][row] = va.y;
            As[kq + 2][row] = va.z; As[kq + 3][row] = va.w;
            int kr = tid >> 4, jq = (tid & 15) * 4;
            float4 vb = *(const float4*)(Wo2 + (size_t)(k0 + kr) * HH + h0 + jq);
            *(float4*)&Bs[kr][jq] = vb;
            __syncthreads();
            #pragma unroll
            for (int k = 0; k < 16; k++) {
                float a[4], b[4];
                #pragma unroll
                for (int i = 0; i < 4; i++) a[i] = As[k][ty * 4 + i];
                #pragma unroll
                for (int i = 0; i < 4; i++) b[i] = Bs[k][tx * 4 + i];
                #pragma unroll
                for (int i = 0; i < 4; i++)
                    #pragma unroll
                    for (int jj = 0; jj < 4; jj++) acc[i][jj] += a[i] * b[jj];
            }
            __syncthreads();
        }
        #pragma unroll
        for (int i = 0; i < 4; i++)
            #pragma unroll
            for (int jj = 0; jj < 4; jj++)
                g_W4[(size_t)(r0 + ty * 4 + i) * KZ + EE + h0 + tx * 4 + jj] = acc[i][jj];
    }
}

// Wait: Wo2 in reference is (E,H); out = u @ Wo2^T means out_e = sum_h Wo2[e,h]*u_h.
// W_U[rr,h] = sum_e W_O[rr,e]*Wo2[e,h]  -> B operand Wo2[e,h] is row-major h-contig: OK above.

// split fp32 -> bf16 hi + lo
__global__ void conv_split(const float* __restrict__ src,
                           unsigned short* __restrict__ hi,
                           unsigned short* __restrict__ lo, int n4) {
    int i = blockIdx.x * 256 + threadIdx.x;
    if (i >= n4) return;
    float4 v = ((const float4*)src)[i];
    __nv_bfloat16 h0 = __float2bfloat16(v.x);
    __nv_bfloat16 h1 = __float2bfloat16(v.y);
    __nv_bfloat16 h2 = __float2bfloat16(v.z);
    __nv_bfloat16 h3 = __float2bfloat16(v.w);
    __nv_bfloat16 l0 = __float2bfloat16(v.x - __bfloat162float(h0));
    __nv_bfloat16 l1 = __float2bfloat16(v.y - __bfloat162float(h1));
    __nv_bfloat16 l2 = __float2bfloat16(v.z - __bfloat162float(h2));
    __nv_bfloat16 l3 = __float2bfloat16(v.w - __bfloat162float(h3));
    __nv_bfloat162* H = (__nv_bfloat162*)hi;
    __nv_bfloat162* L = (__nv_bfloat162*)lo;
    H[2 * i]     = __halves2bfloat162(h0, h1);
    H[2 * i + 1] = __halves2bfloat162(h2, h3);
    L[2 * i]     = __halves2bfloat162(l0, l1);
    L[2 * i + 1] = __halves2bfloat162(l2, l3);
}

// ---------------- persistent decoder loop (3 barriers/step) ----------------
__global__ void __launch_bounds__(256) decoder_loop(
    const float* __restrict__ emb, const void* __restrict__ trg_raw,
    const float* __restrict__ mem,
    const float* __restrict__ Wo1, const float* __restrict__ bo1)
{
    __shared__ union {
        struct { float Zs[64][33]; float2 Wp[64][9]; float Gs[16][33]; int tok[BB]; } a;
        struct { float q[HH]; float sc[128]; float red[2][128]; } c;
        struct { float Zs[128][33]; float Ws[4][130]; float red[4][32]; } d;
    } sm;

    int tid = threadIdx.x, wid = tid >> 5, lane = tid & 31;
    int bid = blockIdx.x;
    int w3 = wid & 3, kh = wid >> 2;

    for (int t = 0; t < TT; t++) {
        const float* u_prev = g_uall + (size_t)(t - 1) * BB * HH;   // unused at t=0
        const float* h_prev = g_h[t & 1];
        float*       h_cur  = g_h[(t + 1) & 1];

        // ---- Phase A: gates = W_E emb + W_U u_prev + W_hh h_prev + bias; LSTM ----
        {
            int rbase = bid * 16;
            if (tid < BB) {
                long long v;
                if (g_trg64) v = ((const long long*)trg_raw)[tid * TT + t];
                else         v = ((const int*)trg_raw)[tid * TT + t];
                int tk = (int)v;
                if (tk < 0) tk = 0;
                if (tk >= VV) tk = VV - 1;
                sm.a.tok[tid] = tk;
            }
            __syncthreads();

            float acc0 = 0.f, acc1 = 0.f;
            for (int kt = 0; kt < KZ / 64; kt++) {
                int kg0 = kt * 64;
                for (int i = tid; i < 2048; i += 256) {
                    int b = i >> 6, k = i & 63, kg = kg0 + k;
                    float v;
                    if      (kg < EE)      v = emb[(size_t)sm.a.tok[b] * EE + kg];
                    else if (kg < 2 * EE)  v = (t == 0) ? 0.f : u_prev[b * HH + (kg - EE)];
                    else                   v = h_prev[b * HH + (kg - 2 * EE)];
                    sm.a.Zs[k][b] = v;
                }
                for (int i = tid; i < 1024; i += 256) {
                    int r = i >> 6, k = i & 63;
                    float v = g_W4[(size_t)(rbase + r) * KZ + kg0 + k];
                    ((float*)sm.a.Wp)[k * 18 + (r & 7) * 2 + (r >> 3)] = v;
                }
                __syncthreads();
                #pragma unroll
                for (int kk = 0; kk < 64; kk++) {
                    float z = sm.a.Zs[kk][lane];
                    float2 wv = sm.a.Wp[kk][wid];
                    acc0 += wv.x * z;
                    acc1 += wv.y * z;
                }
                __syncthreads();
            }
            {
                int r0 = rbase + wid, r1 = rbase + wid + 8;
                float e0 = (t == 0) ? g_c0[r0 * BB + lane] : g_wob2[r0];
                float e1 = (t == 0) ? g_c0[r1 * BB + lane] : g_wob2[r1];
                sm.a.Gs[wid][lane]     = acc0 + g_b4[r0] + e0;
                sm.a.Gs[wid + 8][lane] = acc1 + g_b4[r1] + e1;
            }
            __syncthreads();

            if (tid < 128) {
                int hl = tid >> 5, b = tid & 31;
                float gi = sm.a.Gs[4 * hl + 0][b];
                float gf = sm.a.Gs[4 * hl + 1][b];
                float gg = sm.a.Gs[4 * hl + 2][b];
                float go = sm.a.Gs[4 * hl + 3][b];
                gi = 1.f / (1.f + expf(-gi));
                gf = 1.f / (1.f + expf(-gf));
                go = 1.f / (1.f + expf(-go));
                gg = tanhf(gg);
                int h = bid * 4 + hl;
                int idx = b * HH + h;
                float c = gf * g_c[idx] + gi * gg;
                g_c[idx] = c;
                h_cur[idx] = go * tanhf(c);
            }
        }
        gsync();

        // ---- Phase C: attention; 4 blocks per batch (redundant softmax, split ctx) ----
        {
            int b = bid & 31;
            int slice = bid >> 5;          // 0..3 -> 128 ctx components each
            for (int i = tid; i < HH; i += 256) sm.c.q[i] = h_cur[b * HH + i];
            __syncthreads();

            for (int s = wid; s < SS; s += 8) {
                const float* prow = g_P + (size_t)(b * SS + s) * HH;
                float a = 0.f;
                for (int k = lane; k < HH; k += 32) a += sm.c.q[k] * prow[k];
                #pragma unroll
                for (int off = 16; off; off >>= 1) a += __shfl_down_sync(0xffffffffu, a, off);
                if (lane == 0) sm.c.sc[s] = a + g_q0[b * SS + s];
            }
            __syncthreads();

            if (wid == 0) {
                float m = -1e30f;
                for (int s = lane; s < SS; s += 32) m = fmaxf(m, sm.c.sc[s]);
                #pragma unroll
                for (int off = 16; off; off >>= 1) m = fmaxf(m, __shfl_xor_sync(0xffffffffu, m, off));
                float sum = 0.f;
                for (int s = lane; s < SS; s += 32) {
                    float e = expf(sm.c.sc[s] - m); sm.c.sc[s] = e; sum += e;
                }
                #pragma unroll
                for (int off = 16; off; off >>= 1) sum += __shfl_xor_sync(0xffffffffu, sum, off);
                float inv = 1.f / sum;
                for (int s = lane; s < SS; s += 32) sm.c.sc[s] *= inv;
            }
            __syncthreads();

            {
                int h_local = tid & 127, sh = tid >> 7;   // split s-range in 2
                const float* mbase = mem + (size_t)b * SS * HH + slice * 128 + h_local;
                float a = 0.f;
                int s0 = sh * 50;
                #pragma unroll 5
                for (int s = s0; s < s0 + 50; s++) a += sm.c.sc[s] * mbase[(size_t)s * HH];
                sm.c.red[sh][h_local] = a;
            }
            __syncthreads();
            if (tid < 128)
                g_ctx[b * HH + slice * 128 + tid] = sm.c.red[0][tid] + sm.c.red[1][tid];
        }
        gsync();

        // ---- Phase D1: u = tanh(Wo1 [h|ctx] + bo1); write to uall[t] ----
        {
            int r0 = bid * 4;
            float acc = 0.f;
            for (int kt = 0; kt < 8; kt++) {
                int kgA = kt * 64;
                int kgB = 512 + kt * 64;
                for (int i = tid; i < 4096; i += 256) {
                    int b = i >> 7, kk = i & 127;
                    int kg = (kk < 64) ? (kgA + kk) : (kgB + kk - 64);
                    float v = (kg < HH) ? h_cur[b * HH + kg] : g_ctx[b * HH + (kg - HH)];
                    sm.d.Zs[kk][b] = v;
                }
                for (int i = tid; i < 512; i += 256) {
                    int r = i >> 7, kk = i & 127;
                    int kg = (kk < 64) ? (kgA + kk) : (kgB + kk - 64);
                    sm.d.Ws[r][kk] = Wo1[(size_t)(r0 + r) * (2 * HH) + kg];
                }
                __syncthreads();
                #pragma unroll
                for (int kk = 0; kk < 64; kk++)
                    acc += sm.d.Ws[w3][kh * 64 + kk] * sm.d.Zs[kh * 64 + kk][lane];
                __syncthreads();
            }
            if (kh == 1) sm.d.red[w3][lane] = acc;
            __syncthreads();
            if (kh == 0) {
                acc += sm.d.red[w3][lane];
                g_uall[((size_t)t * BB + lane) * HH + r0 + w3] = tanhf(acc + bo1[r0 + w3]);
            }
        }
        gsync();
    }
}

// ---------------- out = uall(2048,512) @ Wo2(512,512)^T + bo2 ----------------
__global__ void __launch_bounds__(256) out_gemm(const float* __restrict__ Wo2,
                                                const float* __restrict__ bo2)
{
    __shared__ float As[16][68];
    __shared__ float Bs[16][68];
    int tid = threadIdx.x;
    int m0 = blockIdx.y * 64, e0 = blockIdx.x * 64;
    int tx = tid & 15, ty = tid >> 4;

    float acc[4][4];
    #pragma unroll
    for (int i = 0; i < 4; i++)
        #pragma unroll
        for (int j = 0; j < 4; j++) acc[i][j] = 0.f;

    for (int k0 = 0; k0 < HH; k0 += 16) {
        int row = tid >> 2, kq = (tid & 3) * 4;
        float4 va = *(const float4*)(g_uall + (size_t)(m0 + row) * HH + k0 + kq);
        As[kq][row] = va.x; As[kq + 1][row] = va.y;
        As[kq + 2][row] = va.z; As[kq + 3][row] = va.w;
        float4 vb = *(const float4*)(Wo2 + (size_t)(e0 + row) * HH + k0 + kq);
        Bs[kq][row] = vb.x; Bs[kq + 1][row] = vb.y;
        Bs[kq + 2][row] = vb.z; Bs[kq + 3][row] = vb.w;
        __syncthreads();
        #pragma unroll
        for (int k = 0; k < 16; k++) {
            float a[4], b[4];
            #pragma unroll
            for (int i = 0; i < 4; i++) a[i] = As[k][ty * 4 + i];
            #pragma unroll
            for (int i = 0; i < 4; i++) b[i] = Bs[k][tx * 4 + i];
            #pragma unroll
            for (int i = 0; i < 4; i++)
                #pragma unroll
                for (int j = 0; j < 4; j++) acc[i][j] += a[i] * b[j];
        }
        __syncthreads();
    }
    #pragma unroll
    for (int i = 0; i < 4; i++)
        #pragma unroll
        for (int j = 0; j < 4; j++)
            g_out[(size_t)(m0 + ty * 4 + i) * EE + e0 + tx * 4 + j] =
                acc[i][j] + bo2[e0 + tx * 4 + j];
}

// ---------------- HMMA logits GEMM ----------------
#define SPAD 72
__global__ void __launch_bounds__(256, 2) logits_mma(float* __restrict__ outp)
{
    __shared__ __align__(16) unsigned short sA[128 * SPAD];
    __shared__ __align__(16) unsigned short sB[128 * SPAD];

    int tid = threadIdx.x, lane = tid & 31, wid = tid >> 5;
    int wm = wid >> 2;
    int wn = wid & 3;
    int mblk = blockIdx.x * 128;
    int nblk = blockIdx.y * 128;

    uint32_t aA = smem_u32(sA);
    uint32_t aB = smem_u32(sB);
    uint32_t abase = aA + (uint32_t)((wm * 64 + (lane & 15)) * SPAD * 2 + (lane >> 4) * 16);
    uint32_t bbase = aB + (uint32_t)((wn * 32 + (lane & 15)) * SPAD * 2 + (lane >> 4) * 16);

    float acc[4][4][4];
    #pragma unroll
    for (int i = 0; i < 4; i++)
        #pragma unroll
        for (int j = 0; j < 4; j++)
            #pragma unroll
            for (int k = 0; k < 4; k++) acc[i][j][k] = 0.f;

    for (int c = 0; c < 24; c++) {
        int pass = c >> 3;
        int kb = (c & 7) * 64;
        const unsigned short* Ap = (pass == 2) ? g_Al : g_Ah;
        const unsigned short* Bp = (pass == 1) ? g_Bl : g_Bh;

        __syncthreads();
        #pragma unroll
        for (int u = 0; u < 4; u++) {
            int unit = u * 256 + tid;
            int row = unit >> 3, seg = unit & 7;
            uint4 va = *(const uint4*)(Ap + (size_t)(mblk + row) * 512 + kb + seg * 8);
            *(uint4*)(sA + row * SPAD + seg * 8) = va;
            uint4 vb = *(const uint4*)(Bp + (size_t)(nblk + row) * 512 + kb + seg * 8);
            *(uint4*)(sB + row * SPAD + seg * 8) = vb;
        }
        __syncthreads();

        #pragma unroll
        for (int ks = 0; ks < 4; ks++) {
            uint32_t afr[4][4];
            #pragma unroll
            for (int mf = 0; mf < 4; mf++)
                ldm_x4(afr[mf], abase + (uint32_t)(mf * 16 * SPAD * 2 + ks * 32));
            uint32_t bfr[2][4];
            #pragma unroll
            for (int g = 0; g < 2; g++)
                ldm_x4(bfr[g], bbase + (uint32_t)(g * 16 * SPAD * 2 + ks * 32));
            #pragma unroll
            for (int mf = 0; mf < 4; mf++)
                #pragma unroll
                for (int nf = 0; nf < 4; nf++)
                    mma_bf16(acc[mf][nf], afr[mf],
                             bfr[nf >> 1][nf & 1], bfr[nf >> 1][(nf & 1) + 2]);
        }
    }

    #pragma unroll
    for (int mf = 0; mf < 4; mf++) {
        int r0 = mblk + wm * 64 + mf * 16 + (lane >> 2);
        #pragma unroll
        for (int half = 0; half < 2; half++) {
            int r = r0 + half * 8;
            int tt = r >> 5, b2 = r & 31;
            float* orow = outp + (size_t)(b2 * TT + tt) * VV + nblk + wn * 32 + (lane & 3) * 2;
            #pragma unroll
            for (int nf = 0; nf < 4; nf++) {
                float2 v = make_float2(acc[mf][nf][2 * half], acc[mf][nf][2 * half + 1]);
                *(float2*)(orow + nf * 8) = v;
            }
        }
    }
}

// ---------------- host launch ----------------
extern "C" void kernel_launch(void* const* d_in, const int* in_sizes, int n_in,
                              void* d_out, int out_size)
{
    const float* src_memory  = (const float*)d_in[0];
    const void*  src_mask    = d_in[1];
    const float* init_hidden = (const float*)d_in[2];
    const float* init_cell   = (const float*)d_in[3];
    const float* init_output = (const float*)d_in[4];
    const void*  trg         = d_in[5];
    const float* emb         = (const float*)d_in[6];
    const float* W_ih        = (const float*)d_in[7];
    const float* W_hh        = (const float*)d_in[8];
    const float* b_ih        = (const float*)d_in[9];
    const float* b_hh        = (const float*)d_in[10];
    const float* Wq          = (const float*)d_in[11];
    const float* bq          = (const float*)d_in[12];
    const float* Wb          = (const float*)d_in[13];
    const float* bbias       = (const float*)d_in[14];
    const float* Wo1         = (const float*)d_in[15];
    const float* bo1         = (const float*)d_in[16];
    const float* Wo2         = (const float*)d_in[17];
    const float* bo2         = (const float*)d_in[18];

    float *p_out;
    unsigned short *p_Bh, *p_Bl, *p_Ah, *p_Al;
    cudaGetSymbolAddress((void**)&p_out, g_out);
    cudaGetSymbolAddress((void**)&p_Bh,  g_Bh);
    cudaGetSymbolAddress((void**)&p_Bl,  g_Bl);
    cudaGetSymbolAddress((void**)&p_Ah,  g_Ah);
    cudaGetSymbolAddress((void**)&p_Al,  g_Al);

    // #1
    prep1<<<3393, 256>>>((const int*)trg, (const int*)src_mask, init_hidden, init_cell,
                         Wq, Wb, bq, bbias, W_ih, W_hh, b_ih, b_hh, init_output, bo2);
    // #2
    prep2<<<1056, 256>>>(src_memory, src_mask, W_ih, Wo2);
    // #3 (independent; positions decoder_loop at launch #4)
    {
        int n4 = (VV * EE) / 4;
        conv_split<<<(n4 + 255) / 256, 256>>>(emb, p_Bh, p_Bl, n4);
    }
    // #4
    decoder_loop<<<NBLK, 256>>>(emb, trg, src_memory, Wo1, bo1);
    // #5
    out_gemm<<<dim3(EE / 64, (TT * BB) / 64), 256>>>(Wo2, bo2);
    // #6
    {
        int n4 = (TT * BB * EE) / 4;
        conv_split<<<(n4 + 255) / 256, 256>>>(p_out, p_Ah, p_Al, n4);
    }
    // #7
    logits_mma<<<dim3(16, 250), 256>>>((float*)d_out);
}